// round 12
// baseline (speedup 1.0000x reference)
#include <cuda_runtime.h>
#include <cstdint>

#define D 128
#define NVOX (D * D * D)
#define P 130
#define PV (P * P * P)
#define FULL 0xFFFFFFFFu

// zero-padded SoA: (e0, e1, e2, state0) per voxel; shell written as zeros
__device__ float4 g_pack[PV];

// ---------- pass 1: padded transpose (LTS-capped) ----------
__global__ void __launch_bounds__(256)
transpose_kernel(const float* __restrict__ x)
{
    int pv = blockIdx.x * blockDim.x + threadIdx.x;
    if (pv >= PV) return;

    int pk = pv % P;
    int t  = pv / P;
    int pj = t % P;
    int pi = t / P;

    int i = pi - 1, j = pj - 1, k = pk - 1;
    float4 r = make_float4(0.0f, 0.0f, 0.0f, 0.0f);
    if (((unsigned)i < (unsigned)D) &
        ((unsigned)j < (unsigned)D) &
        ((unsigned)k < (unsigned)D)) {
        const float* xv = x + (((long)i * D + j) * D + k) * 5;
        r.x = xv[1];
        r.y = xv[2];
        r.z = xv[3];
        r.w = xv[0];
    }
    g_pack[pv] = r;
}

// ---------- pass 2: update with MLP-4 cooperative gather ----------
__global__ void __launch_bounds__(256)
ca_update_kernel(const float* __restrict__ out, float* __restrict__ y)
{
    __shared__ __align__(16) float ly[256 * 5];

    const int tid  = threadIdx.x;
    const int base = blockIdx.x * 256;
    const int v    = base + tid;
    const int lane = tid & 31;

    const int k = v & (D - 1);
    const int j = (v >> 7) & (D - 1);
    const int i = v >> 14;
    const int pc = ((i + 1) * P + (j + 1)) * P + (k + 1);

    const float4* o4 = reinterpret_cast<const float4*>(out + (size_t)v * 8);
    float4 oa = __ldcs(o4 + 0);
    float4 ob = __ldcs(o4 + 1);

    int   state1 = 0;
    float bst    = oa.x;
    if (oa.y > bst) { bst = oa.y; state1 = 1; }
    if (oa.z > bst) { bst = oa.z; state1 = 2; }
    if (oa.w > bst) { bst = oa.w; state1 = 3; }

    float4 ctr = g_pack[pc];
    int state0 = (int)ctr.w;
    if (state0 == 0) state1 = 0;

    // flag + ballot as early as possible so gather loads issue first
    bool flag = (state0 <= 1) && (state1 > 1);
    unsigned mask = __ballot_sync(FULL, flag);

    int c26 = lane + (lane >= 13 ? 1 : 0);
    int di = c26 / 9 - 1;
    int dj = (c26 / 3) % 3 - 1;
    int dk = c26 % 3 - 1;
    int noff = (di * P + dj) * P + dk;
    const bool gl = (lane < 26);

    float y_e0 = ctr.x;
    float y_e1 = ctr.y;
    float y_e2 = ctr.z;
    float field1 = ob.w;

    while (mask) {
        // pop up to 4 flagged voxels
        int src[4];
        int nb_cnt = 0;
        #pragma unroll
        for (int b = 0; b < 4; b++) {
            src[b] = -1;
            if (mask) { src[b] = __ffs(mask) - 1; mask &= mask - 1; nb_cnt++; }
        }

        // all scattered loads in flight before any dependent use (MLP 4)
        float4 nb[4];
        #pragma unroll
        for (int b = 0; b < 4; b++) {
            int s = __shfl_sync(FULL, pc, src[b] < 0 ? src[0] : src[b]);
            nb[b] = make_float4(0.f, 0.f, 0.f, 0.f);
            if (gl && b < nb_cnt) nb[b] = g_pack[s + noff];
        }

        #pragma unroll
        for (int b = 0; b < 4; b++) {
            if (b >= nb_cnt) break;
            float rx = __shfl_sync(FULL, ob.x, src[b]);
            float ry = __shfl_sync(FULL, ob.y, src[b]);
            float rz = __shfl_sync(FULL, ob.z, src[b]);
            float d0 = nb[b].x - rx;
            float d1 = nb[b].y - ry;
            float d2 = nb[b].z - rz;
            float dist = d0 * d0 + d1 * d1 + d2 * d2;
            unsigned key = gl ? ((__float_as_uint(dist) & ~31u) | lane)
                              : 0xFFFFFFFFu;
            unsigned kmin = __reduce_min_sync(FULL, key);
            int s = (int)(kmin & 31u);
            float w0 = __shfl_sync(FULL, nb[b].x, s);
            float w1 = __shfl_sync(FULL, nb[b].y, s);
            float w2 = __shfl_sync(FULL, nb[b].z, s);
            if (lane == src[b]) { y_e0 = w0; y_e1 = w1; y_e2 = w2; }
        }
    }

    // field/euler masking AFTER the gather (gather result overrides only for
    // flagged voxels, which all have state1 > 1, so ordering is safe:
    // apply masks to the gathered values exactly as reference does)
    if (state1 <= 1) {
        field1 = -1.0f;
        y_e0 = -1.0f; y_e1 = -1.0f; y_e2 = -1.0f;
    } else if (state1 == 2) {
        field1 = fminf(fmaxf(field1, 0.0f), 0.92f);
    } else {
        field1 = 1.0f;
    }

    // staged coalesced float4 output (streaming stores)
    ly[tid * 5 + 0] = (float)state1;
    ly[tid * 5 + 1] = y_e0;
    ly[tid * 5 + 2] = y_e1;
    ly[tid * 5 + 3] = y_e2;
    ly[tid * 5 + 4] = field1;
    __syncthreads();
    {
        float4* yb = reinterpret_cast<float4*>(y + (size_t)base * 5);
        const float4* s4 = reinterpret_cast<const float4*>(ly);
        #pragma unroll
        for (int t = tid; t < 320; t += 256) __stcs(yb + t, s4[t]);
    }
}

extern "C" void kernel_launch(void* const* d_in, const int* in_sizes, int n_in,
                              void* d_out, int out_size)
{
    const float* x   = (const float*)d_in[0];
    const float* out = (const float*)d_in[1];
    if (n_in >= 2 && in_sizes[0] == 8 * NVOX && in_sizes[1] == 5 * NVOX) {
        const float* t = x; x = out; out = t;
    }
    float* y = (float*)d_out;

    transpose_kernel<<<(PV + 255) / 256, 256>>>(x);
    ca_update_kernel<<<NVOX / 256, 256>>>(out, y);
}

// round 13
// speedup vs baseline: 1.1243x; 1.1243x over previous
#include <cuda_runtime.h>
#include <cstdint>

#define D 128
#define NVOX (D * D * D)
#define P 130
#define PV (P * P * P)
#define FULL 0xFFFFFFFFu

// zero-padded SoA: (e0, e1, e2, state0) per voxel; shell written as zeros
__device__ float4 g_pack[PV];

// ---------- pass 1: padded transpose ----------
__global__ void __launch_bounds__(256)
transpose_kernel(const float* __restrict__ x)
{
    int pv = blockIdx.x * blockDim.x + threadIdx.x;
    if (pv >= PV) return;

    int pk = pv % P;
    int t  = pv / P;
    int pj = t % P;
    int pi = t / P;

    int i = pi - 1, j = pj - 1, k = pk - 1;
    float4 r = make_float4(0.0f, 0.0f, 0.0f, 0.0f);
    if (((unsigned)i < (unsigned)D) &
        ((unsigned)j < (unsigned)D) &
        ((unsigned)k < (unsigned)D)) {
        const float* xv = x + (((long)i * D + j) * D + k) * 5;
        r.x = xv[1];
        r.y = xv[2];
        r.z = xv[3];
        r.w = xv[0];
    }
    g_pack[pv] = r;
}

// ---------- pass 2: 4x8x8 tiles, L1-resident cooperative gather ----------
__global__ void __launch_bounds__(256)
ca_update_kernel(const float* __restrict__ out, float* __restrict__ y)
{
    __shared__ __align__(16) float ly[256 * 5];   // [32 rows][40 floats]

    const int tid  = threadIdx.x;
    const int lane = tid & 31;

    // tile decode: 32 x 16 x 16 tiles of 4x8x8
    const int bid = blockIdx.x;
    const int tk = bid & 15;
    const int tj = (bid >> 4) & 15;
    const int ti = bid >> 8;
    const int i0 = ti * 4, j0 = tj * 8, k0 = tk * 8;

    const int li = tid >> 6;
    const int lj = (tid >> 3) & 7;
    const int lk = tid & 7;
    const int gi = i0 + li, gj = j0 + lj, gk = k0 + lk;
    const int v  = (gi * D + gj) * D + gk;
    const int pc = ((gi + 1) * P + (gj + 1)) * P + (gk + 1);

    const float4* o4 = reinterpret_cast<const float4*>(out + (size_t)v * 8);
    float4 oa = __ldcs(o4 + 0);
    float4 ob = __ldcs(o4 + 1);

    int   state1 = 0;
    float bst    = oa.x;
    if (oa.y > bst) { bst = oa.y; state1 = 1; }
    if (oa.z > bst) { bst = oa.z; state1 = 2; }
    if (oa.w > bst) { bst = oa.w; state1 = 3; }

    float4 ctr = g_pack[pc];
    int state0 = (int)ctr.w;
    if (state0 == 0) state1 = 0;

    float y_e0 = ctr.x;
    float y_e1 = ctr.y;
    float y_e2 = ctr.z;

    float field1 = ob.w;
    if (state1 <= 1) {
        field1 = -1.0f;
        y_e0 = -1.0f; y_e1 = -1.0f; y_e2 = -1.0f;
    } else if (state1 == 2) {
        field1 = fminf(fmaxf(field1, 0.0f), 0.92f);
    } else {
        field1 = 1.0f;
    }

    // warp-cooperative 26-neighbor argmin, MLP-2, gathers mostly L1-resident
    bool flag = (state0 <= 1) && (state1 > 1);
    unsigned mask = __ballot_sync(FULL, flag);

    int c26 = lane + (lane >= 13 ? 1 : 0);
    int di = c26 / 9 - 1;
    int dj = (c26 / 3) % 3 - 1;
    int dk = c26 % 3 - 1;
    int noff = (di * P + dj) * P + dk;
    const bool gl = (lane < 26);

    while (mask) {
        int srcA = __ffs(mask) - 1;
        mask &= mask - 1;
        int srcB = -1;
        if (mask) { srcB = __ffs(mask) - 1; mask &= mask - 1; }

        int spcA = __shfl_sync(FULL, pc, srcA);
        int spcB = __shfl_sync(FULL, pc, srcB < 0 ? srcA : srcB);

        float4 nbA = make_float4(0.f, 0.f, 0.f, 0.f);
        float4 nbB = make_float4(0.f, 0.f, 0.f, 0.f);
        if (gl) {
            nbA = g_pack[spcA + noff];
            if (srcB >= 0) nbB = g_pack[spcB + noff];
        }

        float rxA = __shfl_sync(FULL, ob.x, srcA);
        float ryA = __shfl_sync(FULL, ob.y, srcA);
        float rzA = __shfl_sync(FULL, ob.z, srcA);
        {
            float d0 = nbA.x - rxA, d1 = nbA.y - ryA, d2 = nbA.z - rzA;
            float dist = d0 * d0 + d1 * d1 + d2 * d2;
            unsigned key = gl ? ((__float_as_uint(dist) & ~31u) | lane)
                              : 0xFFFFFFFFu;
            unsigned kmin = __reduce_min_sync(FULL, key);
            int s = (int)(kmin & 31u);
            float w0 = __shfl_sync(FULL, nbA.x, s);
            float w1 = __shfl_sync(FULL, nbA.y, s);
            float w2 = __shfl_sync(FULL, nbA.z, s);
            if (lane == srcA) { y_e0 = w0; y_e1 = w1; y_e2 = w2; }
        }
        if (srcB >= 0) {
            float rxB = __shfl_sync(FULL, ob.x, srcB);
            float ryB = __shfl_sync(FULL, ob.y, srcB);
            float rzB = __shfl_sync(FULL, ob.z, srcB);
            float d0 = nbB.x - rxB, d1 = nbB.y - ryB, d2 = nbB.z - rzB;
            float dist = d0 * d0 + d1 * d1 + d2 * d2;
            unsigned key = gl ? ((__float_as_uint(dist) & ~31u) | lane)
                              : 0xFFFFFFFFu;
            unsigned kmin = __reduce_min_sync(FULL, key);
            int s = (int)(kmin & 31u);
            float w0 = __shfl_sync(FULL, nbB.x, s);
            float w1 = __shfl_sync(FULL, nbB.y, s);
            float w2 = __shfl_sync(FULL, nbB.z, s);
            if (lane == srcB) { y_e0 = w0; y_e1 = w1; y_e2 = w2; }
        }
    }

    // stage outputs: row = li*8+lj (0..31), 40 floats per row
    const int row = tid >> 3;
    ly[row * 40 + lk * 5 + 0] = (float)state1;
    ly[row * 40 + lk * 5 + 1] = y_e0;
    ly[row * 40 + lk * 5 + 2] = y_e1;
    ly[row * 40 + lk * 5 + 3] = y_e2;
    ly[row * 40 + lk * 5 + 4] = field1;
    __syncthreads();

    // 32 rows x 10 float4; row base = ((gi*D+gj)*D + k0)*5, 16B-aligned
    for (int f = tid; f < 320; f += 256) {
        int r    = f / 10;
        int part = f - r * 10;
        int ri = i0 + (r >> 3);
        int rj = j0 + (r & 7);
        long gbase = (((long)ri * D + rj) * D + k0) * 5 + part * 4;
        __stcs(reinterpret_cast<float4*>(y + gbase),
               *reinterpret_cast<const float4*>(&ly[r * 40 + part * 4]));
    }
}

extern "C" void kernel_launch(void* const* d_in, const int* in_sizes, int n_in,
                              void* d_out, int out_size)
{
    const float* x   = (const float*)d_in[0];
    const float* out = (const float*)d_in[1];
    if (n_in >= 2 && in_sizes[0] == 8 * NVOX && in_sizes[1] == 5 * NVOX) {
        const float* t = x; x = out; out = t;
    }
    float* y = (float*)d_out;

    transpose_kernel<<<(PV + 255) / 256, 256>>>(x);
    ca_update_kernel<<<8192, 256>>>(out, y);
}